// round 15
// baseline (speedup 1.0000x reference)
#include <cuda_runtime.h>
#include <cuda_bf16.h>
#include <cuda_fp16.h>
#include <math.h>
#include <stdint.h>

#define SEQ 2048
#define HID 4096
#define KDIM 4096
#define NH 32
#define NKV 8
#define HD 128

// ---------------------------------------------------------------------------
// Scratch (device globals: no allocation allowed)
// ---------------------------------------------------------------------------
__device__ float g_q[(size_t)NH * SEQ * HD];
__device__ float g_k[(size_t)NKV * SEQ * HD];
__device__ float g_v[(size_t)NKV * SEQ * HD];

__device__ __nv_bfloat16 g_hs_h[(size_t)SEQ * KDIM];
__device__ __nv_bfloat16 g_hs_l[(size_t)SEQ * KDIM];
__device__ __nv_bfloat16 g_wq_h[(size_t)HID * KDIM];
__device__ __nv_bfloat16 g_wq_l[(size_t)HID * KDIM];
__device__ __nv_bfloat16 g_wk_h[(size_t)NKV * HD * KDIM];
__device__ __nv_bfloat16 g_wk_l[(size_t)NKV * HD * KDIM];
__device__ __nv_bfloat16 g_wv_h[(size_t)NKV * HD * KDIM];
__device__ __nv_bfloat16 g_wv_l[(size_t)NKV * HD * KDIM];
__device__ __nv_bfloat16 g_ao_h[(size_t)SEQ * HID];
__device__ __nv_bfloat16 g_ao_l[(size_t)SEQ * HID];
__device__ __nv_bfloat16 g_wo_h[(size_t)HID * KDIM];
__device__ __nv_bfloat16 g_wo_l[(size_t)HID * KDIM];

// attention operands
__device__ __half g_qh[(size_t)NH * SEQ * HD];   // q hi (fp16, pre-scaled)
__device__ __half g_ql[(size_t)NH * SEQ * HD];   // q lo
__device__ __half g_ki[(size_t)NKV * SEQ * HD];  // k int values (exact in fp16)
__device__ __half g_vi[(size_t)NKV * SEQ * HD];  // v int values
__device__ float  g_ks[(size_t)NKV * SEQ];       // k per-row scale
__device__ float  g_vs[(size_t)NKV * SEQ];       // v per-row scale

// ---------------------------------------------------------------------------
// PTX helpers — baseline ISA only
// ---------------------------------------------------------------------------
__device__ __forceinline__ uint32_t smem_u32(const void* p) {
    uint32_t a;
    asm("{ .reg .u64 t; cvta.to.shared.u64 t, %1; cvt.u32.u64 %0, t; }"
        : "=r"(a) : "l"(p));
    return a;
}

#define CP_ASYNC16(s, g) \
    asm volatile("cp.async.cg.shared.global [%0], [%1], 16;" :: "r"(s), "l"(g))
#define CP_COMMIT() asm volatile("cp.async.commit_group;" ::: "memory")
#define CP_WAIT1()  asm volatile("cp.async.wait_group 1;" ::: "memory")
#define CP_WAIT2()  asm volatile("cp.async.wait_group 2;" ::: "memory")

#define LDMATRIX_X4(r0, r1, r2, r3, a) \
    asm volatile("ldmatrix.sync.aligned.m8n8.x4.shared.b16 {%0,%1,%2,%3}, [%4];" \
                 : "=r"(r0), "=r"(r1), "=r"(r2), "=r"(r3) : "r"(a))

#define LDMATRIX_X4_T(r0, r1, r2, r3, a) \
    asm volatile("ldmatrix.sync.aligned.m8n8.x4.trans.shared.b16 {%0,%1,%2,%3}, [%4];" \
                 : "=r"(r0), "=r"(r1), "=r"(r2), "=r"(r3) : "r"(a))

__device__ __forceinline__ void mma_bf16(float* c, const uint32_t* a, const uint32_t* b)
{
    asm volatile(
        "mma.sync.aligned.m16n8k16.row.col.f32.bf16.bf16.f32 "
        "{%0,%1,%2,%3}, {%4,%5,%6,%7}, {%8,%9}, {%0,%1,%2,%3};"
        : "+f"(c[0]), "+f"(c[1]), "+f"(c[2]), "+f"(c[3])
        : "r"(a[0]), "r"(a[1]), "r"(a[2]), "r"(a[3]), "r"(b[0]), "r"(b[1]));
}

__device__ __forceinline__ void mma_f16(float* c, const uint32_t* a, const uint32_t* b)
{
    asm volatile(
        "mma.sync.aligned.m16n8k16.row.col.f32.f16.f16.f32 "
        "{%0,%1,%2,%3}, {%4,%5,%6,%7}, {%8,%9}, {%0,%1,%2,%3};"
        : "+f"(c[0]), "+f"(c[1]), "+f"(c[2]), "+f"(c[3])
        : "r"(a[0]), "r"(a[1]), "r"(a[2]), "r"(a[3]), "r"(b[0]), "r"(b[1]));
}

__device__ __forceinline__ void split2h(float a, float b, uint32_t& hi, uint32_t& lo)
{
    __half ha = __float2half_rn(a), hb = __float2half_rn(b);
    __half la = __float2half_rn(a - __half2float(ha));
    __half lb = __float2half_rn(b - __half2float(hb));
    __half2 H = __halves2half2(ha, hb), L = __halves2half2(la, lb);
    hi = *reinterpret_cast<uint32_t*>(&H);
    lo = *reinterpret_cast<uint32_t*>(&L);
}

__device__ __forceinline__ void bsplit2(float a, float b,
                                        __nv_bfloat162& hi, __nv_bfloat162& lo)
{
    __nv_bfloat16 ha = __float2bfloat16(a), hb = __float2bfloat16(b);
    __nv_bfloat16 la = __float2bfloat16(a - __bfloat162float(ha));
    __nv_bfloat16 lb = __float2bfloat16(b - __bfloat162float(hb));
    hi = __nv_bfloat162(ha, hb);
    lo = __nv_bfloat162(la, lb);
}

// ---------------------------------------------------------------------------
// fp32 -> (hi, lo) bf16 split. 0=hs 1=wq 2=wk 3=wv 5=wo
// ---------------------------------------------------------------------------
template <int SRC>
__global__ void __launch_bounds__(256) cvt_split(const float* __restrict__ s, int n)
{
    __nv_bfloat16 *hi, *lo;
    if      (SRC == 0) { hi = g_hs_h; lo = g_hs_l; }
    else if (SRC == 1) { hi = g_wq_h; lo = g_wq_l; }
    else if (SRC == 2) { hi = g_wk_h; lo = g_wk_l; }
    else if (SRC == 3) { hi = g_wv_h; lo = g_wv_l; }
    else               { hi = g_wo_h; lo = g_wo_l; }

    size_t i = ((size_t)blockIdx.x * 256 + threadIdx.x) * 4;
    if (i >= (size_t)n) return;
    float4 v = *(const float4*)(s + i);
    __nv_bfloat16 h0 = __float2bfloat16(v.x);
    __nv_bfloat16 h1 = __float2bfloat16(v.y);
    __nv_bfloat16 h2 = __float2bfloat16(v.z);
    __nv_bfloat16 h3 = __float2bfloat16(v.w);
    __nv_bfloat16 l0 = __float2bfloat16(v.x - __bfloat162float(h0));
    __nv_bfloat16 l1 = __float2bfloat16(v.y - __bfloat162float(h1));
    __nv_bfloat16 l2 = __float2bfloat16(v.z - __bfloat162float(h2));
    __nv_bfloat16 l3 = __float2bfloat16(v.w - __bfloat162float(h3));
    *(__nv_bfloat162*)(hi + i)     = __nv_bfloat162(h0, h1);
    *(__nv_bfloat162*)(hi + i + 2) = __nv_bfloat162(h2, h3);
    *(__nv_bfloat162*)(lo + i)     = __nv_bfloat162(l0, l1);
    *(__nv_bfloat162*)(lo + i + 2) = __nv_bfloat162(l2, l3);
}

// ---------------------------------------------------------------------------
// bf16x3 mma.sync GEMM. BK=32 footprint (81,920 B smem) + OCCUPANCY 2:
// two CTAs co-resident per SM hide cp.async waits, barriers, and
// prologue/epilogue bubbles, and fill wave-quantization tails.
// MMA accumulation sequence identical to rounds 9/11 -> bit-identical output.
// CFG: 0 -> Q head-major, 3 -> O row-major into Cout,
//      4 -> fused K+V: blockIdx.z = 0 -> K, 1 -> V (head-major epilogue).
// ---------------------------------------------------------------------------
#define PITCH   80
#define ARRB    (128 * PITCH)        // 10240 B per operand array
#define STAGEB  (4 * ARRB)           // 40960 B
#define GSMEM   (2 * STAGEB)         // 81920 B -> 2 CTAs/SM fit in 228 KB
#define NCHUNK  (KDIM / 32)          // 128

template <int CFG>
__global__ void __launch_bounds__(256, 2) gemm_mma(float* __restrict__ Cout, int N)
{
    extern __shared__ char smem[];
    const __nv_bfloat16 *Ah, *Al, *Bh, *Bl;
    if      (CFG == 0) { Ah = g_hs_h; Al = g_hs_l; Bh = g_wq_h; Bl = g_wq_l; }
    else if (CFG == 3) { Ah = g_ao_h; Al = g_ao_l; Bh = g_wo_h; Bl = g_wo_l; }
    else {
        Ah = g_hs_h; Al = g_hs_l;
        if (blockIdx.z == 0) { Bh = g_wk_h; Bl = g_wk_l; }
        else                 { Bh = g_wv_h; Bl = g_wv_l; }
    }

    const uint32_t sb = smem_u32(smem);
    const int t = threadIdx.x, lane = t & 31, wid = t >> 5;
    const int wm = (wid >> 2) * 64;
    const int wn = (wid & 3) * 32;
    const int bm = blockIdx.y * 128, bn = blockIdx.x * 128;

    const int lr  = t >> 2;
    const int lc16 = (t & 3) * 16;

    const __nv_bfloat16* gsrc[4] = {Ah, Al, Bh, Bl};
    const int rbase[4] = {bm, bm, bn, bn};

    auto load_chunk = [&](int c, int s) {
        const int k0 = c * 32;
        const uint32_t so = sb + (uint32_t)s * STAGEB;
#pragma unroll
        for (int a = 0; a < 4; a++) {
#pragma unroll
            for (int j = 0; j < 2; j++) {
                const int r = lr + j * 64;
                const __nv_bfloat16* g =
                    gsrc[a] + (size_t)(rbase[a] + r) * KDIM + k0 + (lc16 >> 1);
                CP_ASYNC16(so + a * ARRB + r * PITCH + lc16, g);
            }
        }
    };

    float acc[4][4][4];
#pragma unroll
    for (int i = 0; i < 4; i++)
#pragma unroll
        for (int j = 0; j < 4; j++)
#pragma unroll
            for (int r = 0; r < 4; r++) acc[i][j][r] = 0.f;

    load_chunk(0, 0); CP_COMMIT();
    load_chunk(1, 1); CP_COMMIT();

    const uint32_t a_off = (uint32_t)(lane & 15) * PITCH + (uint32_t)(lane >> 4) * 16;
    const uint32_t b_off = (uint32_t)((lane >> 4) * 8 + (lane & 7)) * PITCH
                         + (uint32_t)((lane >> 3) & 1) * 16;

    for (int c = 0; c < NCHUNK; c++) {
        CP_WAIT1();
        __syncthreads();
        const uint32_t so = sb + (uint32_t)(c & 1) * STAGEB;

#pragma unroll
        for (int ks = 0; ks < 2; ks++) {
            const uint32_t kb = ks * 32;
            uint32_t ah[4][4], al[4][4], bh[4][2], bl[4][2];
#pragma unroll
            for (int mf = 0; mf < 4; mf++) {
                const uint32_t ra = (uint32_t)(wm + mf * 16) * PITCH + kb + a_off;
                LDMATRIX_X4(ah[mf][0], ah[mf][1], ah[mf][2], ah[mf][3], so + ra);
                LDMATRIX_X4(al[mf][0], al[mf][1], al[mf][2], al[mf][3], so + ARRB + ra);
            }
#pragma unroll
            for (int nf = 0; nf < 4; nf += 2) {
                const uint32_t rb = (uint32_t)(wn + nf * 8) * PITCH + kb + b_off;
                LDMATRIX_X4(bh[nf][0], bh[nf][1], bh[nf + 1][0], bh[nf + 1][1],
                            so + 2 * ARRB + rb);
                LDMATRIX_X4(bl[nf][0], bl[nf][1], bl[nf + 1][0], bl[nf + 1][1],
                            so + 3 * ARRB + rb);
            }
#pragma unroll
            for (int mf = 0; mf < 4; mf++)
#pragma unroll
                for (int nf = 0; nf < 4; nf++) {
                    mma_bf16(acc[mf][nf], ah[mf], bh[nf]);
                    mma_bf16(acc[mf][nf], ah[mf], bl[nf]);
                    mma_bf16(acc[mf][nf], al[mf], bh[nf]);
                }
        }
        __syncthreads();
        if (c + 2 < NCHUNK) load_chunk(c + 2, c & 1);
        CP_COMMIT();
    }

    // Epilogue: float2 stores (r-pairs are adjacent n; col0 is even)
#pragma unroll
    for (int mf = 0; mf < 4; mf++) {
        const int row0 = bm + wm + mf * 16 + (lane >> 2);
#pragma unroll
        for (int nf = 0; nf < 4; nf++) {
            const int col0 = bn + wn + nf * 8 + (lane & 3) * 2;
#pragma unroll
            for (int half = 0; half < 2; half++) {
                const int m = row0 + half * 8;
                const float2 v2 = make_float2(acc[mf][nf][half * 2],
                                              acc[mf][nf][half * 2 + 1]);
                if (CFG == 3) {
                    *(float2*)(Cout + (size_t)m * N + col0) = v2;
                } else if (CFG == 0) {
                    *(float2*)(g_q + ((size_t)(col0 >> 7) * SEQ + m) * HD + (col0 & 127)) = v2;
                } else {
                    float* C = (blockIdx.z == 0) ? g_k : g_v;
                    *(float2*)(C + ((size_t)(col0 >> 7) * SEQ + m) * HD + (col0 & 127)) = v2;
                }
            }
        }
    }
}

// ---------------------------------------------------------------------------
// RoPE + int8 sym quant. One WARP per row; amax via warp shuffle.
// ---------------------------------------------------------------------------
__device__ __forceinline__ void rope_pair(float x1, float x2, float pos, int d,
                                          float& y1, float& y2)
{
    const float th = pos * expf(-logf(10000.f) * (float)(2 * d) * (1.f / 128.f));
    float s, c;
    sincosf(th, &s, &c);
    y1 = x1 * c - x2 * s;
    y2 = x2 * c + x1 * s;
}

__global__ void __launch_bounds__(256) rope_q_kernel()
{
    const int w = threadIdx.x >> 5, lane = threadIdx.x & 31;
    const int row = blockIdx.x * 8 + w;
    const int m   = row & (SEQ - 1);
    const float* p = g_q + (size_t)row * HD;
    const float x0 = p[lane], x1 = p[lane + 32], x2 = p[lane + 64], x3 = p[lane + 96];
    float y0, y1, y2, y3;
    rope_pair(x0, x2, (float)m, lane,      y0, y2);
    rope_pair(x1, x3, (float)m, lane + 32, y1, y3);
    const float sc = 0.08838834764831845f;  // 1/sqrt(128)
    y0 *= sc; y1 *= sc; y2 *= sc; y3 *= sc;

    __half* qh = g_qh + (size_t)row * HD;
    __half* ql = g_ql + (size_t)row * HD;
    const float v[4] = {y0, y1, y2, y3};
#pragma unroll
    for (int i = 0; i < 4; i++) {
        __half h = __float2half_rn(v[i]);
        qh[lane + 32 * i] = h;
        ql[lane + 32 * i] = __float2half_rn(v[i] - __half2float(h));
    }
}

__global__ void __launch_bounds__(256) rope_quant_k_kernel()
{
    const int w = threadIdx.x >> 5, lane = threadIdx.x & 31;
    const int row = blockIdx.x * 8 + w;
    const int m   = row & (SEQ - 1);
    const float* p = g_k + (size_t)row * HD;
    const float x0 = p[lane], x1 = p[lane + 32], x2 = p[lane + 64], x3 = p[lane + 96];
    float y0, y1, y2, y3;
    rope_pair(x0, x2, (float)m, lane,      y0, y2);
    rope_pair(x1, x3, (float)m, lane + 32, y1, y3);

    float amax = fmaxf(fmaxf(fabsf(y0), fabsf(y1)), fmaxf(fabsf(y2), fabsf(y3)));
#pragma unroll
    for (int off = 16; off; off >>= 1)
        amax = fmaxf(amax, __shfl_xor_sync(0xffffffffu, amax, off));

    const float scale = fmaxf(amax * (1.f / 127.f), 1e-9f);
    const float inv   = 1.f / scale;
    __half* ki = g_ki + (size_t)row * HD;
    const float v[4] = {y0, y1, y2, y3};
#pragma unroll
    for (int i = 0; i < 4; i++)
        ki[lane + 32 * i] = __float2half_rn(fminf(fmaxf(rintf(v[i] * inv), -128.f), 127.f));
    if (lane == 0) g_ks[row] = scale;
}

__global__ void __launch_bounds__(256) quant_v_kernel()
{
    const int w = threadIdx.x >> 5, lane = threadIdx.x & 31;
    const int row = blockIdx.x * 8 + w;
    const float* p = g_v + (size_t)row * HD;
    const float v0 = p[lane], v1 = p[lane + 32], v2 = p[lane + 64], v3 = p[lane + 96];

    float amax = fmaxf(fmaxf(fabsf(v0), fabsf(v1)), fmaxf(fabsf(v2), fabsf(v3)));
#pragma unroll
    for (int off = 16; off; off >>= 1)
        amax = fmaxf(amax, __shfl_xor_sync(0xffffffffu, amax, off));

    const float scale = fmaxf(amax * (1.f / 127.f), 1e-9f);
    const float inv   = 1.f / scale;
    __half* vi = g_vi + (size_t)row * HD;
    const float v[4] = {v0, v1, v2, v3};
#pragma unroll
    for (int i = 0; i < 4; i++)
        vi[lane + 32 * i] = __float2half_rn(fminf(fmaxf(rintf(v[i] * inv), -128.f), 127.f));
    if (lane == 0) g_vs[row] = scale;
}

// ---------------------------------------------------------------------------
// Tensor-core flash attention (unchanged from passing rounds 9/11).
// ---------------------------------------------------------------------------
#define AP      272
#define QTILE   (64 * AP)
#define KVSTAGE (2 * QTILE + 512)
#define ASMEM   (2 * QTILE + 2 * KVSTAGE)

__global__ void __launch_bounds__(128) attn_tc()
{
    extern __shared__ char smem[];
    const uint32_t sb = smem_u32(smem);
    const int h   = blockIdx.x;
    const int q0  = blockIdx.y * 64;
    const int kvh = h >> 2;
    const int t = threadIdx.x, lane = t & 31, w = t >> 5;

    {
        const char* qh_g = (const char*)(g_qh + ((size_t)h * SEQ + q0) * HD);
        const char* ql_g = (const char*)(g_ql + ((size_t)h * SEQ + q0) * HD);
#pragma unroll
        for (int p = 0; p < 8; p++) {
            const int id = p * 128 + t;
            const int r = id >> 4, c = (id & 15) * 16;
            CP_ASYNC16(sb + r * AP + c, qh_g + r * 256 + c);
            CP_ASYNC16(sb + QTILE + r * AP + c, ql_g + r * 256 + c);
        }
        CP_COMMIT();
    }

    const char* kg  = (const char*)(g_ki + (size_t)kvh * SEQ * HD);
    const char* vg  = (const char*)(g_vi + (size_t)kvh * SEQ * HD);
    const char* skg = (const char*)(g_ks + (size_t)kvh * SEQ);
    const char* svg = (const char*)(g_vs + (size_t)kvh * SEQ);

    const int nkt = q0 / 64 + 1;

    auto load_kv = [&](int kt, int s) {
        const uint32_t so = sb + 2 * QTILE + (uint32_t)s * KVSTAGE;
#pragma unroll
        for (int p = 0; p < 8; p++) {
            const int id = p * 128 + t;
            const int r = id >> 4, c = (id & 15) * 16;
            CP_ASYNC16(so + r * AP + c, kg + (size_t)(kt + r) * 256 + c);
            CP_ASYNC16(so + QTILE + r * AP + c, vg + (size_t)(kt + r) * 256 + c);
        }
        if (t < 16)       CP_ASYNC16(so + 2 * QTILE + t * 16,        skg + (size_t)kt * 4 + t * 16);
        else if (t < 32)  CP_ASYNC16(so + 2 * QTILE + 256 + (t - 16) * 16,
                                     svg + (size_t)kt * 4 + (t - 16) * 16);
    };

    load_kv(0, 0); CP_COMMIT();
    if (nkt > 1) load_kv(64, 1);
    CP_COMMIT();

    CP_WAIT2();
    __syncthreads();
    uint32_t qh[8][4], ql[8][4];
    {
        const uint32_t a_off = (uint32_t)(lane & 15) * AP + (uint32_t)(lane >> 4) * 16;
        const uint32_t qb = sb + (uint32_t)(16 * w) * AP + a_off;
#pragma unroll
        for (int kf = 0; kf < 8; kf++) {
            LDMATRIX_X4(qh[kf][0], qh[kf][1], qh[kf][2], qh[kf][3], qb + kf * 32);
            LDMATRIX_X4(ql[kf][0], ql[kf][1], ql[kf][2], ql[kf][3], qb + QTILE + kf * 32);
        }
    }

    float m0 = -1e30f, m1 = -1e30f, l0 = 0.f, l1 = 0.f;
    float o[16][4];
#pragma unroll
    for (int i = 0; i < 16; i++) { o[i][0] = o[i][1] = o[i][2] = o[i][3] = 0.f; }

    const int r0 = q0 + 16 * w + (lane >> 2);
    const uint32_t b_off = (uint32_t)((lane >> 4) * 8 + (lane & 7)) * AP
                         + (uint32_t)((lane >> 3) & 1) * 16;

    for (int i = 0; i < nkt; i++) {
        CP_WAIT1();
        __syncthreads();
        const uint32_t kb = sb + 2 * QTILE + (uint32_t)(i & 1) * KVSTAGE;
        const uint32_t vb_base = kb + QTILE;
        const float* sks = (const float*)(smem + 2 * QTILE + (size_t)(i & 1) * KVSTAGE + 2 * QTILE);
        const float* svs = sks + 64;

        float sc[8][4];
#pragma unroll
        for (int nf = 0; nf < 8; nf++) sc[nf][0] = sc[nf][1] = sc[nf][2] = sc[nf][3] = 0.f;
#pragma unroll
        for (int kf = 0; kf < 8; kf++) {
            uint32_t b[8][2];
#pragma unroll
            for (int nf = 0; nf < 8; nf += 2)
                LDMATRIX_X4(b[nf][0], b[nf][1], b[nf + 1][0], b[nf + 1][1],
                            kb + (uint32_t)(nf * 8) * AP + kf * 32 + b_off);
#pragma unroll
            for (int nf = 0; nf < 8; nf++) {
                mma_f16(sc[nf], qh[kf], b[nf]);
                mma_f16(sc[nf], ql[kf], b[nf]);
            }
        }

        const bool diag = (i == nkt - 1);
        float mx0 = -1e30f, mx1 = -1e30f;
#pragma unroll
        for (int nf = 0; nf < 8; nf++) {
            const int c0 = nf * 8 + 2 * (lane & 3);
            const float2 sk2 = *(const float2*)(sks + c0);
            float s0 = sc[nf][0] * sk2.x;
            float s1 = sc[nf][1] * sk2.y;
            float s2 = sc[nf][2] * sk2.x;
            float s3 = sc[nf][3] * sk2.y;
            if (diag) {
                const int j = i * 64 + c0;
                if (j > r0)         s0 = -1e9f;
                if (j + 1 > r0)     s1 = -1e9f;
                if (j > r0 + 8)     s2 = -1e9f;
                if (j + 1 > r0 + 8) s3 = -1e9f;
            }
            sc[nf][0] = s0; sc[nf][1] = s1; sc[nf][2] = s2; sc[nf][3] = s3;
            mx0 = fmaxf(mx0, fmaxf(s0, s1));
            mx1 = fmaxf(mx1, fmaxf(s2, s3));
        }
        mx0 = fmaxf(mx0, __shfl_xor_sync(0xffffffffu, mx0, 1));
        mx0 = fmaxf(mx0, __shfl_xor_sync(0xffffffffu, mx0, 2));
        mx1 = fmaxf(mx1, __shfl_xor_sync(0xffffffffu, mx1, 1));
        mx1 = fmaxf(mx1, __shfl_xor_sync(0xffffffffu, mx1, 2));
        const float mn0 = fmaxf(m0, mx0), mn1 = fmaxf(m1, mx1);
        const float cr0 = __expf(m0 - mn0), cr1 = __expf(m1 - mn1);
        m0 = mn0; m1 = mn1;

        float sm0 = 0.f, sm1 = 0.f;
        uint32_t pa[4][4], pb[4][4];
#pragma unroll
        for (int nf = 0; nf < 8; nf++) {
            const int c0 = nf * 8 + 2 * (lane & 3);
            float p0 = __expf(sc[nf][0] - mn0);
            float p1 = __expf(sc[nf][1] - mn0);
            float p2 = __expf(sc[nf][2] - mn1);
            float p3 = __expf(sc[nf][3] - mn1);
            sm0 += p0 + p1; sm1 += p2 + p3;
            const float2 sv2 = *(const float2*)(svs + c0);
            p0 *= sv2.x; p1 *= sv2.y; p2 *= sv2.x; p3 *= sv2.y;
            uint32_t h01, l01, h23, l23;
            split2h(p0, p1, h01, l01);
            split2h(p2, p3, h23, l23);
            const int jf = nf >> 1, e = (nf & 1) * 2;
            pa[jf][e] = h01; pa[jf][e + 1] = h23;
            pb[jf][e] = l01; pb[jf][e + 1] = l23;
        }
        sm0 += __shfl_xor_sync(0xffffffffu, sm0, 1);
        sm0 += __shfl_xor_sync(0xffffffffu, sm0, 2);
        sm1 += __shfl_xor_sync(0xffffffffu, sm1, 1);
        sm1 += __shfl_xor_sync(0xffffffffu, sm1, 2);
        l0 = l0 * cr0 + sm0;
        l1 = l1 * cr1 + sm1;
#pragma unroll
        for (int df = 0; df < 16; df++) {
            o[df][0] *= cr0; o[df][1] *= cr0; o[df][2] *= cr1; o[df][3] *= cr1;
        }

#pragma unroll
        for (int jf = 0; jf < 4; jf++) {
            uint32_t vf[16][2];
            const uint32_t vrow = (uint32_t)(jf * 16 + (lane & 7) + ((lane >> 3) & 1) * 8) * AP;
#pragma unroll
            for (int df = 0; df < 16; df += 2)
                LDMATRIX_X4_T(vf[df][0], vf[df][1], vf[df + 1][0], vf[df + 1][1],
                              vb_base + vrow + (uint32_t)(df * 8 + (lane >> 4) * 8) * 2);
#pragma unroll
            for (int df = 0; df < 16; df++) {
                mma_f16(o[df], pa[jf], vf[df]);
                mma_f16(o[df], pb[jf], vf[df]);
            }
        }

        __syncthreads();
        if (i + 2 < nkt) load_kv((i + 2) * 64, i & 1);
        CP_COMMIT();
    }

    const float il0 = 1.f / l0, il1 = 1.f / l1;
#pragma unroll
    for (int df = 0; df < 16; df++) {
        const int d = df * 8 + 2 * (lane & 3);
        const size_t b0 = (size_t)r0 * HID + (size_t)h * HD + d;
        const size_t b1 = b0 + 8 * HID;
        __nv_bfloat162 hh, ll;
        bsplit2(o[df][0] * il0, o[df][1] * il0, hh, ll);
        *(__nv_bfloat162*)(g_ao_h + b0) = hh;
        *(__nv_bfloat162*)(g_ao_l + b0) = ll;
        bsplit2(o[df][2] * il1, o[df][3] * il1, hh, ll);
        *(__nv_bfloat162*)(g_ao_h + b1) = hh;
        *(__nv_bfloat162*)(g_ao_l + b1) = ll;
    }
}

// ---------------------------------------------------------------------------
// Launch. Inputs resolved by SIZE SIGNATURE (robust to metadata order).
// ---------------------------------------------------------------------------
extern "C" void kernel_launch(void* const* d_in, const int* in_sizes, int n_in,
                              void* d_out, int out_size)
{
    (void)n_in; (void)out_size;
    const float* hs;
    const float* wq; const float* wk; const float* wv; const float* wo;

    if (in_sizes[5] == 2048) {                 // dict insertion order
        hs = (const float*)d_in[0];
        wq = (const float*)d_in[1];
        wk = (const float*)d_in[2];
        wv = (const float*)d_in[3];
        wo = (const float*)d_in[4];
    } else {                                   // alphabetical order
        hs = (const float*)d_in[0];
        wk = (const float*)d_in[2];
        wo = (const float*)d_in[3];
        wq = (const float*)d_in[4];
        wv = (const float*)d_in[5];
    }
    float* out = (float*)d_out;

    cudaFuncSetAttribute((const void*)gemm_mma<0>, cudaFuncAttributeMaxDynamicSharedMemorySize, GSMEM);
    cudaFuncSetAttribute((const void*)gemm_mma<3>, cudaFuncAttributeMaxDynamicSharedMemorySize, GSMEM);
    cudaFuncSetAttribute((const void*)gemm_mma<4>, cudaFuncAttributeMaxDynamicSharedMemorySize, GSMEM);
    cudaFuncSetAttribute((const void*)attn_tc,     cudaFuncAttributeMaxDynamicSharedMemorySize, ASMEM);

    // Split fp32 operands into bf16 hi/lo
    cvt_split<0><<<(SEQ * KDIM) / 1024, 256>>>(hs, SEQ * KDIM);
    cvt_split<1><<<(HID * KDIM) / 1024, 256>>>(wq, HID * KDIM);
    cvt_split<2><<<(NKV * HD * KDIM) / 1024, 256>>>(wk, NKV * HD * KDIM);
    cvt_split<3><<<(NKV * HD * KDIM) / 1024, 256>>>(wv, NKV * HD * KDIM);
    cvt_split<5><<<(HID * KDIM) / 1024, 256>>>(wo, HID * KDIM);

    // QKV projections (bf16x3 mma.sync, occ-2); K+V fused in one launch
    gemm_mma<0><<<dim3(HID / 128, SEQ / 128), 256, GSMEM>>>(nullptr, HID);
    gemm_mma<4><<<dim3((NKV * HD) / 128, SEQ / 128, 2), 256, GSMEM>>>(nullptr, NKV * HD);

    // RoPE + quant (warp-per-row, shuffle-only reductions)
    rope_q_kernel<<<(NH * SEQ) / 8, 256>>>();
    rope_quant_k_kernel<<<(NKV * SEQ) / 8, 256>>>();
    quant_v_kernel<<<(NKV * SEQ) / 8, 256>>>();

    // Tensor-core flash attention (writes g_ao_h / g_ao_l directly)
    attn_tc<<<dim3(NH, SEQ / 64), 128, ASMEM>>>();

    // O projection -> d_out
    gemm_mma<3><<<dim3(HID / 128, SEQ / 128), 256, GSMEM>>>(out, HID);
}

// round 16
// speedup vs baseline: 1.0012x; 1.0012x over previous
#include <cuda_runtime.h>
#include <cuda_bf16.h>
#include <cuda_fp16.h>
#include <math.h>
#include <stdint.h>

#define SEQ 2048
#define HID 4096
#define KDIM 4096
#define NH 32
#define NKV 8
#define HD 128

// ---------------------------------------------------------------------------
// Scratch (device globals: no allocation allowed)
// ---------------------------------------------------------------------------
__device__ float g_q[(size_t)NH * SEQ * HD];
__device__ float g_k[(size_t)NKV * SEQ * HD];
__device__ float g_v[(size_t)NKV * SEQ * HD];

__device__ __nv_bfloat16 g_hs_h[(size_t)SEQ * KDIM];
__device__ __nv_bfloat16 g_hs_l[(size_t)SEQ * KDIM];
__device__ __nv_bfloat16 g_wq_h[(size_t)HID * KDIM];
__device__ __nv_bfloat16 g_wq_l[(size_t)HID * KDIM];
__device__ __nv_bfloat16 g_wk_h[(size_t)NKV * HD * KDIM];
__device__ __nv_bfloat16 g_wk_l[(size_t)NKV * HD * KDIM];
__device__ __nv_bfloat16 g_wv_h[(size_t)NKV * HD * KDIM];
__device__ __nv_bfloat16 g_wv_l[(size_t)NKV * HD * KDIM];
__device__ __nv_bfloat16 g_ao_h[(size_t)SEQ * HID];
__device__ __nv_bfloat16 g_ao_l[(size_t)SEQ * HID];
__device__ __nv_bfloat16 g_wo_h[(size_t)HID * KDIM];
__device__ __nv_bfloat16 g_wo_l[(size_t)HID * KDIM];

// attention operands
__device__ __half g_qh[(size_t)NH * SEQ * HD];   // q hi (fp16, pre-scaled)
__device__ __half g_ql[(size_t)NH * SEQ * HD];   // q lo
__device__ __half g_ki[(size_t)NKV * SEQ * HD];  // k int values (exact in fp16)
__device__ __half g_vi[(size_t)NKV * SEQ * HD];  // v int values
__device__ float  g_ks[(size_t)NKV * SEQ];       // k per-row scale
__device__ float  g_vs[(size_t)NKV * SEQ];       // v per-row scale

// ---------------------------------------------------------------------------
// PTX helpers — baseline ISA only
// ---------------------------------------------------------------------------
__device__ __forceinline__ uint32_t smem_u32(const void* p) {
    uint32_t a;
    asm("{ .reg .u64 t; cvta.to.shared.u64 t, %1; cvt.u32.u64 %0, t; }"
        : "=r"(a) : "l"(p));
    return a;
}

#define CP_ASYNC16(s, g) \
    asm volatile("cp.async.cg.shared.global [%0], [%1], 16;" :: "r"(s), "l"(g))
#define CP_COMMIT() asm volatile("cp.async.commit_group;" ::: "memory")
#define CP_WAIT1()  asm volatile("cp.async.wait_group 1;" ::: "memory")
#define CP_WAIT2()  asm volatile("cp.async.wait_group 2;" ::: "memory")

#define LDMATRIX_X4(r0, r1, r2, r3, a) \
    asm volatile("ldmatrix.sync.aligned.m8n8.x4.shared.b16 {%0,%1,%2,%3}, [%4];" \
                 : "=r"(r0), "=r"(r1), "=r"(r2), "=r"(r3) : "r"(a))

#define LDMATRIX_X4_T(r0, r1, r2, r3, a) \
    asm volatile("ldmatrix.sync.aligned.m8n8.x4.trans.shared.b16 {%0,%1,%2,%3}, [%4];" \
                 : "=r"(r0), "=r"(r1), "=r"(r2), "=r"(r3) : "r"(a))

__device__ __forceinline__ void mma_bf16(float* c, const uint32_t* a, const uint32_t* b)
{
    asm volatile(
        "mma.sync.aligned.m16n8k16.row.col.f32.bf16.bf16.f32 "
        "{%0,%1,%2,%3}, {%4,%5,%6,%7}, {%8,%9}, {%0,%1,%2,%3};"
        : "+f"(c[0]), "+f"(c[1]), "+f"(c[2]), "+f"(c[3])
        : "r"(a[0]), "r"(a[1]), "r"(a[2]), "r"(a[3]), "r"(b[0]), "r"(b[1]));
}

__device__ __forceinline__ void mma_f16(float* c, const uint32_t* a, const uint32_t* b)
{
    asm volatile(
        "mma.sync.aligned.m16n8k16.row.col.f32.f16.f16.f32 "
        "{%0,%1,%2,%3}, {%4,%5,%6,%7}, {%8,%9}, {%0,%1,%2,%3};"
        : "+f"(c[0]), "+f"(c[1]), "+f"(c[2]), "+f"(c[3])
        : "r"(a[0]), "r"(a[1]), "r"(a[2]), "r"(a[3]), "r"(b[0]), "r"(b[1]));
}

__device__ __forceinline__ void split2h(float a, float b, uint32_t& hi, uint32_t& lo)
{
    __half ha = __float2half_rn(a), hb = __float2half_rn(b);
    __half la = __float2half_rn(a - __half2float(ha));
    __half lb = __float2half_rn(b - __half2float(hb));
    __half2 H = __halves2half2(ha, hb), L = __halves2half2(la, lb);
    hi = *reinterpret_cast<uint32_t*>(&H);
    lo = *reinterpret_cast<uint32_t*>(&L);
}

__device__ __forceinline__ void bsplit2(float a, float b,
                                        __nv_bfloat162& hi, __nv_bfloat162& lo)
{
    __nv_bfloat16 ha = __float2bfloat16(a), hb = __float2bfloat16(b);
    __nv_bfloat16 la = __float2bfloat16(a - __bfloat162float(ha));
    __nv_bfloat16 lb = __float2bfloat16(b - __bfloat162float(hb));
    hi = __nv_bfloat162(ha, hb);
    lo = __nv_bfloat162(la, lb);
}

// ---------------------------------------------------------------------------
// fp32 -> (hi, lo) bf16 split. 0=hs 1=wq 2=wk 3=wv 5=wo
// ---------------------------------------------------------------------------
template <int SRC>
__global__ void __launch_bounds__(256) cvt_split(const float* __restrict__ s, int n)
{
    __nv_bfloat16 *hi, *lo;
    if      (SRC == 0) { hi = g_hs_h; lo = g_hs_l; }
    else if (SRC == 1) { hi = g_wq_h; lo = g_wq_l; }
    else if (SRC == 2) { hi = g_wk_h; lo = g_wk_l; }
    else if (SRC == 3) { hi = g_wv_h; lo = g_wv_l; }
    else               { hi = g_wo_h; lo = g_wo_l; }

    size_t i = ((size_t)blockIdx.x * 256 + threadIdx.x) * 4;
    if (i >= (size_t)n) return;
    float4 v = *(const float4*)(s + i);
    __nv_bfloat16 h0 = __float2bfloat16(v.x);
    __nv_bfloat16 h1 = __float2bfloat16(v.y);
    __nv_bfloat16 h2 = __float2bfloat16(v.z);
    __nv_bfloat16 h3 = __float2bfloat16(v.w);
    __nv_bfloat16 l0 = __float2bfloat16(v.x - __bfloat162float(h0));
    __nv_bfloat16 l1 = __float2bfloat16(v.y - __bfloat162float(h1));
    __nv_bfloat16 l2 = __float2bfloat16(v.z - __bfloat162float(h2));
    __nv_bfloat16 l3 = __float2bfloat16(v.w - __bfloat162float(h3));
    *(__nv_bfloat162*)(hi + i)     = __nv_bfloat162(h0, h1);
    *(__nv_bfloat162*)(hi + i + 2) = __nv_bfloat162(h2, h3);
    *(__nv_bfloat162*)(lo + i)     = __nv_bfloat162(l0, l1);
    *(__nv_bfloat162*)(lo + i + 2) = __nv_bfloat162(l2, l3);
}

// ---------------------------------------------------------------------------
// bf16x3 mma.sync GEMM. BK=32 footprint (81,920 B smem) + OCCUPANCY 2:
// two CTAs co-resident per SM hide cp.async waits, barriers, and
// prologue/epilogue bubbles, and fill wave-quantization tails.
// MMA accumulation sequence identical to rounds 9/11 -> bit-identical output.
// CFG: 0 -> Q head-major, 3 -> O row-major into Cout,
//      4 -> fused K+V: blockIdx.z = 0 -> K, 1 -> V (head-major epilogue).
// ---------------------------------------------------------------------------
#define PITCH   80
#define ARRB    (128 * PITCH)        // 10240 B per operand array
#define STAGEB  (4 * ARRB)           // 40960 B
#define GSMEM   (2 * STAGEB)         // 81920 B -> 2 CTAs/SM fit in 228 KB
#define NCHUNK  (KDIM / 32)          // 128

template <int CFG>
__global__ void __launch_bounds__(256, 2) gemm_mma(float* __restrict__ Cout, int N)
{
    extern __shared__ char smem[];
    const __nv_bfloat16 *Ah, *Al, *Bh, *Bl;
    if      (CFG == 0) { Ah = g_hs_h; Al = g_hs_l; Bh = g_wq_h; Bl = g_wq_l; }
    else if (CFG == 3) { Ah = g_ao_h; Al = g_ao_l; Bh = g_wo_h; Bl = g_wo_l; }
    else {
        Ah = g_hs_h; Al = g_hs_l;
        if (blockIdx.z == 0) { Bh = g_wk_h; Bl = g_wk_l; }
        else                 { Bh = g_wv_h; Bl = g_wv_l; }
    }

    const uint32_t sb = smem_u32(smem);
    const int t = threadIdx.x, lane = t & 31, wid = t >> 5;
    const int wm = (wid >> 2) * 64;
    const int wn = (wid & 3) * 32;
    const int bm = blockIdx.y * 128, bn = blockIdx.x * 128;

    const int lr  = t >> 2;
    const int lc16 = (t & 3) * 16;

    const __nv_bfloat16* gsrc[4] = {Ah, Al, Bh, Bl};
    const int rbase[4] = {bm, bm, bn, bn};

    auto load_chunk = [&](int c, int s) {
        const int k0 = c * 32;
        const uint32_t so = sb + (uint32_t)s * STAGEB;
#pragma unroll
        for (int a = 0; a < 4; a++) {
#pragma unroll
            for (int j = 0; j < 2; j++) {
                const int r = lr + j * 64;
                const __nv_bfloat16* g =
                    gsrc[a] + (size_t)(rbase[a] + r) * KDIM + k0 + (lc16 >> 1);
                CP_ASYNC16(so + a * ARRB + r * PITCH + lc16, g);
            }
        }
    };

    float acc[4][4][4];
#pragma unroll
    for (int i = 0; i < 4; i++)
#pragma unroll
        for (int j = 0; j < 4; j++)
#pragma unroll
            for (int r = 0; r < 4; r++) acc[i][j][r] = 0.f;

    load_chunk(0, 0); CP_COMMIT();
    load_chunk(1, 1); CP_COMMIT();

    const uint32_t a_off = (uint32_t)(lane & 15) * PITCH + (uint32_t)(lane >> 4) * 16;
    const uint32_t b_off = (uint32_t)((lane >> 4) * 8 + (lane & 7)) * PITCH
                         + (uint32_t)((lane >> 3) & 1) * 16;

    for (int c = 0; c < NCHUNK; c++) {
        CP_WAIT1();
        __syncthreads();
        const uint32_t so = sb + (uint32_t)(c & 1) * STAGEB;

#pragma unroll
        for (int ks = 0; ks < 2; ks++) {
            const uint32_t kb = ks * 32;
            uint32_t ah[4][4], al[4][4], bh[4][2], bl[4][2];
#pragma unroll
            for (int mf = 0; mf < 4; mf++) {
                const uint32_t ra = (uint32_t)(wm + mf * 16) * PITCH + kb + a_off;
                LDMATRIX_X4(ah[mf][0], ah[mf][1], ah[mf][2], ah[mf][3], so + ra);
                LDMATRIX_X4(al[mf][0], al[mf][1], al[mf][2], al[mf][3], so + ARRB + ra);
            }
#pragma unroll
            for (int nf = 0; nf < 4; nf += 2) {
                const uint32_t rb = (uint32_t)(wn + nf * 8) * PITCH + kb + b_off;
                LDMATRIX_X4(bh[nf][0], bh[nf][1], bh[nf + 1][0], bh[nf + 1][1],
                            so + 2 * ARRB + rb);
                LDMATRIX_X4(bl[nf][0], bl[nf][1], bl[nf + 1][0], bl[nf + 1][1],
                            so + 3 * ARRB + rb);
            }
#pragma unroll
            for (int mf = 0; mf < 4; mf++)
#pragma unroll
                for (int nf = 0; nf < 4; nf++) {
                    mma_bf16(acc[mf][nf], ah[mf], bh[nf]);
                    mma_bf16(acc[mf][nf], ah[mf], bl[nf]);
                    mma_bf16(acc[mf][nf], al[mf], bh[nf]);
                }
        }
        __syncthreads();
        if (c + 2 < NCHUNK) load_chunk(c + 2, c & 1);
        CP_COMMIT();
    }

    // Epilogue: float2 stores (r-pairs are adjacent n; col0 is even)
#pragma unroll
    for (int mf = 0; mf < 4; mf++) {
        const int row0 = bm + wm + mf * 16 + (lane >> 2);
#pragma unroll
        for (int nf = 0; nf < 4; nf++) {
            const int col0 = bn + wn + nf * 8 + (lane & 3) * 2;
#pragma unroll
            for (int half = 0; half < 2; half++) {
                const int m = row0 + half * 8;
                const float2 v2 = make_float2(acc[mf][nf][half * 2],
                                              acc[mf][nf][half * 2 + 1]);
                if (CFG == 3) {
                    *(float2*)(Cout + (size_t)m * N + col0) = v2;
                } else if (CFG == 0) {
                    *(float2*)(g_q + ((size_t)(col0 >> 7) * SEQ + m) * HD + (col0 & 127)) = v2;
                } else {
                    float* C = (blockIdx.z == 0) ? g_k : g_v;
                    *(float2*)(C + ((size_t)(col0 >> 7) * SEQ + m) * HD + (col0 & 127)) = v2;
                }
            }
        }
    }
}

// ---------------------------------------------------------------------------
// RoPE + int8 sym quant. One WARP per row; amax via warp shuffle.
// ---------------------------------------------------------------------------
__device__ __forceinline__ void rope_pair(float x1, float x2, float pos, int d,
                                          float& y1, float& y2)
{
    const float th = pos * expf(-logf(10000.f) * (float)(2 * d) * (1.f / 128.f));
    float s, c;
    sincosf(th, &s, &c);
    y1 = x1 * c - x2 * s;
    y2 = x2 * c + x1 * s;
}

__global__ void __launch_bounds__(256) rope_q_kernel()
{
    const int w = threadIdx.x >> 5, lane = threadIdx.x & 31;
    const int row = blockIdx.x * 8 + w;
    const int m   = row & (SEQ - 1);
    const float* p = g_q + (size_t)row * HD;
    const float x0 = p[lane], x1 = p[lane + 32], x2 = p[lane + 64], x3 = p[lane + 96];
    float y0, y1, y2, y3;
    rope_pair(x0, x2, (float)m, lane,      y0, y2);
    rope_pair(x1, x3, (float)m, lane + 32, y1, y3);
    const float sc = 0.08838834764831845f;  // 1/sqrt(128)
    y0 *= sc; y1 *= sc; y2 *= sc; y3 *= sc;

    __half* qh = g_qh + (size_t)row * HD;
    __half* ql = g_ql + (size_t)row * HD;
    const float v[4] = {y0, y1, y2, y3};
#pragma unroll
    for (int i = 0; i < 4; i++) {
        __half h = __float2half_rn(v[i]);
        qh[lane + 32 * i] = h;
        ql[lane + 32 * i] = __float2half_rn(v[i] - __half2float(h));
    }
}

__global__ void __launch_bounds__(256) rope_quant_k_kernel()
{
    const int w = threadIdx.x >> 5, lane = threadIdx.x & 31;
    const int row = blockIdx.x * 8 + w;
    const int m   = row & (SEQ - 1);
    const float* p = g_k + (size_t)row * HD;
    const float x0 = p[lane], x1 = p[lane + 32], x2 = p[lane + 64], x3 = p[lane + 96];
    float y0, y1, y2, y3;
    rope_pair(x0, x2, (float)m, lane,      y0, y2);
    rope_pair(x1, x3, (float)m, lane + 32, y1, y3);

    float amax = fmaxf(fmaxf(fabsf(y0), fabsf(y1)), fmaxf(fabsf(y2), fabsf(y3)));
#pragma unroll
    for (int off = 16; off; off >>= 1)
        amax = fmaxf(amax, __shfl_xor_sync(0xffffffffu, amax, off));

    const float scale = fmaxf(amax * (1.f / 127.f), 1e-9f);
    const float inv   = 1.f / scale;
    __half* ki = g_ki + (size_t)row * HD;
    const float v[4] = {y0, y1, y2, y3};
#pragma unroll
    for (int i = 0; i < 4; i++)
        ki[lane + 32 * i] = __float2half_rn(fminf(fmaxf(rintf(v[i] * inv), -128.f), 127.f));
    if (lane == 0) g_ks[row] = scale;
}

__global__ void __launch_bounds__(256) quant_v_kernel()
{
    const int w = threadIdx.x >> 5, lane = threadIdx.x & 31;
    const int row = blockIdx.x * 8 + w;
    const float* p = g_v + (size_t)row * HD;
    const float v0 = p[lane], v1 = p[lane + 32], v2 = p[lane + 64], v3 = p[lane + 96];

    float amax = fmaxf(fmaxf(fabsf(v0), fabsf(v1)), fmaxf(fabsf(v2), fabsf(v3)));
#pragma unroll
    for (int off = 16; off; off >>= 1)
        amax = fmaxf(amax, __shfl_xor_sync(0xffffffffu, amax, off));

    const float scale = fmaxf(amax * (1.f / 127.f), 1e-9f);
    const float inv   = 1.f / scale;
    __half* vi = g_vi + (size_t)row * HD;
    const float v[4] = {v0, v1, v2, v3};
#pragma unroll
    for (int i = 0; i < 4; i++)
        vi[lane + 32 * i] = __float2half_rn(fminf(fmaxf(rintf(v[i] * inv), -128.f), 127.f));
    if (lane == 0) g_vs[row] = scale;
}

// ---------------------------------------------------------------------------
// Tensor-core flash attention (unchanged from passing rounds 9/11).
// ---------------------------------------------------------------------------
#define AP      272
#define QTILE   (64 * AP)
#define KVSTAGE (2 * QTILE + 512)
#define ASMEM   (2 * QTILE + 2 * KVSTAGE)

__global__ void __launch_bounds__(128) attn_tc()
{
    extern __shared__ char smem[];
    const uint32_t sb = smem_u32(smem);
    const int h   = blockIdx.x;
    const int q0  = blockIdx.y * 64;
    const int kvh = h >> 2;
    const int t = threadIdx.x, lane = t & 31, w = t >> 5;

    {
        const char* qh_g = (const char*)(g_qh + ((size_t)h * SEQ + q0) * HD);
        const char* ql_g = (const char*)(g_ql + ((size_t)h * SEQ + q0) * HD);
#pragma unroll
        for (int p = 0; p < 8; p++) {
            const int id = p * 128 + t;
            const int r = id >> 4, c = (id & 15) * 16;
            CP_ASYNC16(sb + r * AP + c, qh_g + r * 256 + c);
            CP_ASYNC16(sb + QTILE + r * AP + c, ql_g + r * 256 + c);
        }
        CP_COMMIT();
    }

    const char* kg  = (const char*)(g_ki + (size_t)kvh * SEQ * HD);
    const char* vg  = (const char*)(g_vi + (size_t)kvh * SEQ * HD);
    const char* skg = (const char*)(g_ks + (size_t)kvh * SEQ);
    const char* svg = (const char*)(g_vs + (size_t)kvh * SEQ);

    const int nkt = q0 / 64 + 1;

    auto load_kv = [&](int kt, int s) {
        const uint32_t so = sb + 2 * QTILE + (uint32_t)s * KVSTAGE;
#pragma unroll
        for (int p = 0; p < 8; p++) {
            const int id = p * 128 + t;
            const int r = id >> 4, c = (id & 15) * 16;
            CP_ASYNC16(so + r * AP + c, kg + (size_t)(kt + r) * 256 + c);
            CP_ASYNC16(so + QTILE + r * AP + c, vg + (size_t)(kt + r) * 256 + c);
        }
        if (t < 16)       CP_ASYNC16(so + 2 * QTILE + t * 16,        skg + (size_t)kt * 4 + t * 16);
        else if (t < 32)  CP_ASYNC16(so + 2 * QTILE + 256 + (t - 16) * 16,
                                     svg + (size_t)kt * 4 + (t - 16) * 16);
    };

    load_kv(0, 0); CP_COMMIT();
    if (nkt > 1) load_kv(64, 1);
    CP_COMMIT();

    CP_WAIT2();
    __syncthreads();
    uint32_t qh[8][4], ql[8][4];
    {
        const uint32_t a_off = (uint32_t)(lane & 15) * AP + (uint32_t)(lane >> 4) * 16;
        const uint32_t qb = sb + (uint32_t)(16 * w) * AP + a_off;
#pragma unroll
        for (int kf = 0; kf < 8; kf++) {
            LDMATRIX_X4(qh[kf][0], qh[kf][1], qh[kf][2], qh[kf][3], qb + kf * 32);
            LDMATRIX_X4(ql[kf][0], ql[kf][1], ql[kf][2], ql[kf][3], qb + QTILE + kf * 32);
        }
    }

    float m0 = -1e30f, m1 = -1e30f, l0 = 0.f, l1 = 0.f;
    float o[16][4];
#pragma unroll
    for (int i = 0; i < 16; i++) { o[i][0] = o[i][1] = o[i][2] = o[i][3] = 0.f; }

    const int r0 = q0 + 16 * w + (lane >> 2);
    const uint32_t b_off = (uint32_t)((lane >> 4) * 8 + (lane & 7)) * AP
                         + (uint32_t)((lane >> 3) & 1) * 16;

    for (int i = 0; i < nkt; i++) {
        CP_WAIT1();
        __syncthreads();
        const uint32_t kb = sb + 2 * QTILE + (uint32_t)(i & 1) * KVSTAGE;
        const uint32_t vb_base = kb + QTILE;
        const float* sks = (const float*)(smem + 2 * QTILE + (size_t)(i & 1) * KVSTAGE + 2 * QTILE);
        const float* svs = sks + 64;

        float sc[8][4];
#pragma unroll
        for (int nf = 0; nf < 8; nf++) sc[nf][0] = sc[nf][1] = sc[nf][2] = sc[nf][3] = 0.f;
#pragma unroll
        for (int kf = 0; kf < 8; kf++) {
            uint32_t b[8][2];
#pragma unroll
            for (int nf = 0; nf < 8; nf += 2)
                LDMATRIX_X4(b[nf][0], b[nf][1], b[nf + 1][0], b[nf + 1][1],
                            kb + (uint32_t)(nf * 8) * AP + kf * 32 + b_off);
#pragma unroll
            for (int nf = 0; nf < 8; nf++) {
                mma_f16(sc[nf], qh[kf], b[nf]);
                mma_f16(sc[nf], ql[kf], b[nf]);
            }
        }

        const bool diag = (i == nkt - 1);
        float mx0 = -1e30f, mx1 = -1e30f;
#pragma unroll
        for (int nf = 0; nf < 8; nf++) {
            const int c0 = nf * 8 + 2 * (lane & 3);
            const float2 sk2 = *(const float2*)(sks + c0);
            float s0 = sc[nf][0] * sk2.x;
            float s1 = sc[nf][1] * sk2.y;
            float s2 = sc[nf][2] * sk2.x;
            float s3 = sc[nf][3] * sk2.y;
            if (diag) {
                const int j = i * 64 + c0;
                if (j > r0)         s0 = -1e9f;
                if (j + 1 > r0)     s1 = -1e9f;
                if (j > r0 + 8)     s2 = -1e9f;
                if (j + 1 > r0 + 8) s3 = -1e9f;
            }
            sc[nf][0] = s0; sc[nf][1] = s1; sc[nf][2] = s2; sc[nf][3] = s3;
            mx0 = fmaxf(mx0, fmaxf(s0, s1));
            mx1 = fmaxf(mx1, fmaxf(s2, s3));
        }
        mx0 = fmaxf(mx0, __shfl_xor_sync(0xffffffffu, mx0, 1));
        mx0 = fmaxf(mx0, __shfl_xor_sync(0xffffffffu, mx0, 2));
        mx1 = fmaxf(mx1, __shfl_xor_sync(0xffffffffu, mx1, 1));
        mx1 = fmaxf(mx1, __shfl_xor_sync(0xffffffffu, mx1, 2));
        const float mn0 = fmaxf(m0, mx0), mn1 = fmaxf(m1, mx1);
        const float cr0 = __expf(m0 - mn0), cr1 = __expf(m1 - mn1);
        m0 = mn0; m1 = mn1;

        float sm0 = 0.f, sm1 = 0.f;
        uint32_t pa[4][4], pb[4][4];
#pragma unroll
        for (int nf = 0; nf < 8; nf++) {
            const int c0 = nf * 8 + 2 * (lane & 3);
            float p0 = __expf(sc[nf][0] - mn0);
            float p1 = __expf(sc[nf][1] - mn0);
            float p2 = __expf(sc[nf][2] - mn1);
            float p3 = __expf(sc[nf][3] - mn1);
            sm0 += p0 + p1; sm1 += p2 + p3;
            const float2 sv2 = *(const float2*)(svs + c0);
            p0 *= sv2.x; p1 *= sv2.y; p2 *= sv2.x; p3 *= sv2.y;
            uint32_t h01, l01, h23, l23;
            split2h(p0, p1, h01, l01);
            split2h(p2, p3, h23, l23);
            const int jf = nf >> 1, e = (nf & 1) * 2;
            pa[jf][e] = h01; pa[jf][e + 1] = h23;
            pb[jf][e] = l01; pb[jf][e + 1] = l23;
        }
        sm0 += __shfl_xor_sync(0xffffffffu, sm0, 1);
        sm0 += __shfl_xor_sync(0xffffffffu, sm0, 2);
        sm1 += __shfl_xor_sync(0xffffffffu, sm1, 1);
        sm1 += __shfl_xor_sync(0xffffffffu, sm1, 2);
        l0 = l0 * cr0 + sm0;
        l1 = l1 * cr1 + sm1;
#pragma unroll
        for (int df = 0; df < 16; df++) {
            o[df][0] *= cr0; o[df][1] *= cr0; o[df][2] *= cr1; o[df][3] *= cr1;
        }

#pragma unroll
        for (int jf = 0; jf < 4; jf++) {
            uint32_t vf[16][2];
            const uint32_t vrow = (uint32_t)(jf * 16 + (lane & 7) + ((lane >> 3) & 1) * 8) * AP;
#pragma unroll
            for (int df = 0; df < 16; df += 2)
                LDMATRIX_X4_T(vf[df][0], vf[df][1], vf[df + 1][0], vf[df + 1][1],
                              vb_base + vrow + (uint32_t)(df * 8 + (lane >> 4) * 8) * 2);
#pragma unroll
            for (int df = 0; df < 16; df++) {
                mma_f16(o[df], pa[jf], vf[df]);
                mma_f16(o[df], pb[jf], vf[df]);
            }
        }

        __syncthreads();
        if (i + 2 < nkt) load_kv((i + 2) * 64, i & 1);
        CP_COMMIT();
    }

    const float il0 = 1.f / l0, il1 = 1.f / l1;
#pragma unroll
    for (int df = 0; df < 16; df++) {
        const int d = df * 8 + 2 * (lane & 3);
        const size_t b0 = (size_t)r0 * HID + (size_t)h * HD + d;
        const size_t b1 = b0 + 8 * HID;
        __nv_bfloat162 hh, ll;
        bsplit2(o[df][0] * il0, o[df][1] * il0, hh, ll);
        *(__nv_bfloat162*)(g_ao_h + b0) = hh;
        *(__nv_bfloat162*)(g_ao_l + b0) = ll;
        bsplit2(o[df][2] * il1, o[df][3] * il1, hh, ll);
        *(__nv_bfloat162*)(g_ao_h + b1) = hh;
        *(__nv_bfloat162*)(g_ao_l + b1) = ll;
    }
}

// ---------------------------------------------------------------------------
// Launch. Inputs resolved by SIZE SIGNATURE (robust to metadata order).
// ---------------------------------------------------------------------------
extern "C" void kernel_launch(void* const* d_in, const int* in_sizes, int n_in,
                              void* d_out, int out_size)
{
    (void)n_in; (void)out_size;
    const float* hs;
    const float* wq; const float* wk; const float* wv; const float* wo;

    if (in_sizes[5] == 2048) {                 // dict insertion order
        hs = (const float*)d_in[0];
        wq = (const float*)d_in[1];
        wk = (const float*)d_in[2];
        wv = (const float*)d_in[3];
        wo = (const float*)d_in[4];
    } else {                                   // alphabetical order
        hs = (const float*)d_in[0];
        wk = (const float*)d_in[2];
        wo = (const float*)d_in[3];
        wq = (const float*)d_in[4];
        wv = (const float*)d_in[5];
    }
    float* out = (float*)d_out;

    cudaFuncSetAttribute((const void*)gemm_mma<0>, cudaFuncAttributeMaxDynamicSharedMemorySize, GSMEM);
    cudaFuncSetAttribute((const void*)gemm_mma<3>, cudaFuncAttributeMaxDynamicSharedMemorySize, GSMEM);
    cudaFuncSetAttribute((const void*)gemm_mma<4>, cudaFuncAttributeMaxDynamicSharedMemorySize, GSMEM);
    cudaFuncSetAttribute((const void*)attn_tc,     cudaFuncAttributeMaxDynamicSharedMemorySize, ASMEM);

    // Split fp32 operands into bf16 hi/lo
    cvt_split<0><<<(SEQ * KDIM) / 1024, 256>>>(hs, SEQ * KDIM);
    cvt_split<1><<<(HID * KDIM) / 1024, 256>>>(wq, HID * KDIM);
    cvt_split<2><<<(NKV * HD * KDIM) / 1024, 256>>>(wk, NKV * HD * KDIM);
    cvt_split<3><<<(NKV * HD * KDIM) / 1024, 256>>>(wv, NKV * HD * KDIM);
    cvt_split<5><<<(HID * KDIM) / 1024, 256>>>(wo, HID * KDIM);

    // QKV projections (bf16x3 mma.sync, occ-2); K+V fused in one launch
    gemm_mma<0><<<dim3(HID / 128, SEQ / 128), 256, GSMEM>>>(nullptr, HID);
    gemm_mma<4><<<dim3((NKV * HD) / 128, SEQ / 128, 2), 256, GSMEM>>>(nullptr, NKV * HD);

    // RoPE + quant (warp-per-row, shuffle-only reductions)
    rope_q_kernel<<<(NH * SEQ) / 8, 256>>>();
    rope_quant_k_kernel<<<(NKV * SEQ) / 8, 256>>>();
    quant_v_kernel<<<(NKV * SEQ) / 8, 256>>>();

    // Tensor-core flash attention (writes g_ao_h / g_ao_l directly)
    attn_tc<<<dim3(NH, SEQ / 64), 128, ASMEM>>>();

    // O projection -> d_out
    gemm_mma<3><<<dim3(HID / 128, SEQ / 128), 256, GSMEM>>>(out, HID);
}